// round 16
// baseline (speedup 1.0000x reference)
#include <cuda_runtime.h>
#include <cuda_fp16.h>
#include <cstdint>

#define NB_MAX 782            // ceil(100000/128)

// ---------------- device scratch (no allocs allowed) ----------------
// W1 pre-swizzled fp16 (single term): [kt=4][N=256 rows][128B] = 32KB per kt; by-half at by*16384
__device__ __align__(16) unsigned char g_W1sw[4 * 32768];
// W2 pre-swizzled fp16 (single term): [kt=2][16KB]
__device__ __align__(16) unsigned char g_W2sw[2 * 16384];
// h1 per-tile A images (single fp16): [ck=2][16KB] = 32KB per 128-row tile
__device__ __align__(16) unsigned char g_h1img[(size_t)NB_MAX * 32768];
// per-tile completion flags (0..2), zeroed by prep each launch
__device__ int g_done[NB_MAX];

// ---------------- helpers ----------------
__device__ __forceinline__ uint32_t s2u(const void* p) {
    uint32_t a;
    asm("{ .reg .u64 t; cvta.to.shared.u64 t, %1; cvt.u32.u64 %0, t; }" : "=r"(a) : "l"(p));
    return a;
}
#define SW128(o) ((o) ^ (((o) >> 3) & 0x70))

#define LDSM4(R0, R1, R2, R3, A) \
    asm volatile("ldmatrix.sync.aligned.m8n8.x4.shared.b16 {%0,%1,%2,%3}, [%4];" \
                 : "=r"(R0), "=r"(R1), "=r"(R2), "=r"(R3) : "r"(A))

__device__ __forceinline__ void mma_f16(float d[4], const uint32_t a[4], const uint32_t b[2]) {
    asm volatile(
        "mma.sync.aligned.m16n8k16.row.col.f32.f16.f16.f32 "
        "{%0,%1,%2,%3}, {%4,%5,%6,%7}, {%8,%9}, {%0,%1,%2,%3};"
        : "+f"(d[0]), "+f"(d[1]), "+f"(d[2]), "+f"(d[3])
        : "r"(a[0]), "r"(a[1]), "r"(a[2]), "r"(a[3]), "r"(b[0]), "r"(b[1]));
}

__device__ __forceinline__ void cpa16(uint32_t saddr, const void* g) {
    asm volatile("cp.async.cg.shared.global [%0], [%1], 16;" :: "r"(saddr), "l"(g));
}
#define CP_COMMIT() asm volatile("cp.async.commit_group;" ::: "memory")
#define CP_WAIT0()  asm volatile("cp.async.wait_group 0;" ::: "memory")

__device__ __forceinline__ uint2 cvt4h(float4 v) {
    __half2 p0 = __floats2half2_rn(v.x, v.y);
    __half2 p1 = __floats2half2_rn(v.z, v.w);
    uint2 r;
    r.x = *reinterpret_cast<uint32_t*>(&p0);
    r.y = *reinterpret_cast<uint32_t*>(&p1);
    return r;
}

// h = relu( sigmoid(-uz) * tanh(uh) )   [GRU cell with h0 = 0]
__device__ __forceinline__ float gate_act(float uz, float uh) {
    float s = 1.0f / (1.0f + __expf(uz));
    float t = tanhf(uh);
    return fmaxf(s * t, 0.0f);
}

// ---------------- prep: combine W[0,0]+W[1,0], interleave z/h cols, single fp16, swizzle ----------------
__global__ void prep_kernel(const float* __restrict__ wz1, const float* __restrict__ wh1,
                            const float* __restrict__ wz2, const float* __restrict__ wh2) {
    int i = blockIdx.x * blockDim.x + threadIdx.x;   // 65536 threads
    if (i < NB_MAX) g_done[i] = 0;                   // reset flags every launch
    {   // W1: B operand [n=256][k=256]; n=2j -> z_j, n=2j+1 -> h_j
        int nn = i >> 8, k = i & 255;
        int j = nn >> 1;
        const float* src = (nn & 1) ? wh1 : wz1;
        float w = src[k * 128 + j] + src[49152 + k * 128 + j];
        int kt = k >> 6, kk = k & 63;
        uint32_t o = (uint32_t)(kt * 32768) + SW128((uint32_t)(nn * 128 + kk * 2));
        *(__half*)(g_W1sw + o) = __float2half_rn(w);
    }
    if (i < 16384) {   // W2: [n=128][k=128], single fp16
        int nn = i >> 7, k = i & 127;
        int j = nn >> 1;
        const float* src = (nn & 1) ? wh2 : wz2;
        float w = src[k * 64 + j] + src[12288 + k * 64 + j];
        int kt = k >> 6, kk = k & 63;
        uint32_t o = (uint32_t)(kt * 16384) + SW128((uint32_t)(nn * 128 + kk * 2));
        *(__half*)(g_W2sw + o) = __float2half_rn(w);
    }
}

// =================== persistent fused kernel, CTA-resident weights ===================
// Unit list: u in [0, 2*nb)  -> layer1 half-tile (bx = u>>1, by = u&1)
//            u in [2*nb, 3*nb) -> layer2 tile (bx = u - 2*nb), waits on g_done[bx]==2
// Even grid => u&1 constant per CTA => one W1 half per CTA, loaded ONCE.
// SMEM (103040B), occ 2:
//   [0] A0 16K  [16384] A1 16K
//   [32768] B-resident 64K: layer1 = W1half (kt at 32768+kt*16384);
//                           layer2 = W2 in [32768,65536), h2s overlays [65536,98304)
//   tail: [98304] w3s 4K [102400] b3s 64 [102464] w4s 64 [102528] bz2s 256 [102784] bh2s 256
#define SM_BYTES 103040

__global__ void __launch_bounds__(256, 2)
fused_persist(const float* __restrict__ x,
              const float* __restrict__ bz1, const float* __restrict__ bh1,
              const float* __restrict__ bz2, const float* __restrict__ bh2,
              const float* __restrict__ w3, const float* __restrict__ b3,
              const float* __restrict__ w4, const float* __restrict__ b4,
              float* __restrict__ out, int n, int nb) {
    extern __shared__ __align__(128) char sm[];
    const uint32_t sb = s2u(sm);
    const int tid = threadIdx.x, l = tid & 31, w = tid >> 5;
    const int wm = w >> 1, wn = w & 1;          // 4x2 warp grid, warp tile 32x64

    float* w3s  = (float*)(sm + 98304);
    float* b3s  = (float*)(sm + 102400);
    float* w4s  = (float*)(sm + 102464);
    float* bz2s = (float*)(sm + 102528);
    float* bh2s = (float*)(sm + 102784);
#pragma unroll
    for (int i = 0; i < 4; i++) w3s[tid + i * 256] = w3[tid + i * 256];
    if (tid < 16) { b3s[tid] = b3[tid]; w4s[tid] = w4[tid]; }
    if (tid < 64) { bz2s[tid] = bz2[tid]; bh2s[tid] = bh2[tid]; }
    __syncthreads();

    // lane geometry (shared by both paths)
    const int arow0 = wm * 32 + (l & 15);
    const uint32_t kba = (uint32_t)(((l >> 4) & 1) * 16);
    const int brow0 = wn * 64 + 8 * ((l >> 4) & 1) + (l & 7);
    const uint32_t kbb = (uint32_t)(((l >> 3) & 1) * 16);
    const int iq = tid & 15;

    const int NL1 = nb * 2;
    const int NTOT = nb * 3;

    int loadedB = -1;   // -1 none; 0/1 = W1 half; 2 = W2

    for (int u = blockIdx.x; u < NTOT; u += gridDim.x) {
        if (u < NL1) {
            // ================= layer1 half-tile =================
            const int bx = u >> 1, by = u & 1;
            const int r0 = bx * 128;

            if (loadedB != by) {   // once per CTA (even grid => by constant)
                const char* gB = (const char*)g_W1sw + (size_t)by * 16384;
#pragma unroll
                for (int kt = 0; kt < 4; kt++) {
                    const char* s = gB + (size_t)kt * 32768;
                    uint32_t d = sb + 32768u + (uint32_t)kt * 16384u;
#pragma unroll
                    for (int i = 0; i < 4; i++) {
                        int idx = tid + i * 256;
                        cpa16(d + (uint32_t)idx * 16u, s + (size_t)idx * 16);
                    }
                }
                CP_COMMIT();
                CP_WAIT0();
                __syncthreads();
                loadedB = by;
            }

            float acc[2][8][4];
#pragma unroll
            for (int mi = 0; mi < 2; mi++)
#pragma unroll
                for (int nj = 0; nj < 8; nj++)
#pragma unroll
                    for (int q = 0; q < 4; q++) acc[mi][nj][q] = 0.0f;

            uint2 xh[8];
#pragma unroll
            for (int p = 0; p < 8; p++) {
                int gr = r0 + (tid >> 4) + p * 16; if (gr >= n) gr = n - 1;
                xh[p] = cvt4h(*(const float4*)(x + (size_t)gr * 256 + iq * 4));
            }

            for (int kt = 0; kt < 4; kt++) {
                const uint32_t aB = (uint32_t)(kt & 1) * 16384u;
                const uint32_t bB = 32768u + (uint32_t)kt * 16384u;

#pragma unroll
                for (int p = 0; p < 8; p++) {
                    int row = (tid >> 4) + p * 16;
                    uint32_t o = aB + SW128((uint32_t)(row * 128 + iq * 8));
                    *(uint2*)(sm + o) = xh[p];
                }
                if (kt < 3) {
#pragma unroll
                    for (int p = 0; p < 8; p++) {
                        int gr = r0 + (tid >> 4) + p * 16; if (gr >= n) gr = n - 1;
                        xh[p] = cvt4h(*(const float4*)(x + (size_t)gr * 256 + (kt + 1) * 64 + iq * 4));
                    }
                }
                __syncthreads();

#pragma unroll
                for (int kk = 0; kk < 4; kk++) {
                    uint32_t af[2][4], bfr[8][2];
#pragma unroll
                    for (int mi = 0; mi < 2; mi++) {
                        int row = arow0 + mi * 16;
                        uint32_t off = (uint32_t)(row * 128) + (((uint32_t)(kk * 32) + kba) ^ (uint32_t)((row & 7) << 4));
                        LDSM4(af[mi][0], af[mi][1], af[mi][2], af[mi][3], sb + aB + off);
                    }
#pragma unroll
                    for (int g = 0; g < 4; g++) {
                        int row = brow0 + g * 16;
                        uint32_t off = (uint32_t)(row * 128) + (((uint32_t)(kk * 32) + kbb) ^ (uint32_t)((row & 7) << 4));
                        LDSM4(bfr[2 * g][0], bfr[2 * g][1], bfr[2 * g + 1][0], bfr[2 * g + 1][1], sb + bB + off);
                    }
#pragma unroll
                    for (int mi = 0; mi < 2; mi++)
#pragma unroll
                        for (int nj = 0; nj < 8; nj++) mma_f16(acc[mi][nj], af[mi], bfr[nj]);
                }
            }

            // epilogue: act -> fp16, stage half-image in A0 (free: kt=3 computed from A1)
#pragma unroll
            for (int mi = 0; mi < 2; mi++)
#pragma unroll
                for (int nj = 0; nj < 8; nj++) {
                    int rlo = wm * 32 + mi * 16 + (l >> 2);
                    int j = by * 64 + wn * 32 + nj * 4 + (l & 3);
                    float v0 = gate_act(acc[mi][nj][0] + __ldg(bz1 + j), acc[mi][nj][1] + __ldg(bh1 + j));
                    float v1 = gate_act(acc[mi][nj][2] + __ldg(bz1 + j), acc[mi][nj][3] + __ldg(bh1 + j));
                    int kk2 = j & 63;
                    uint32_t o0 = SW128((uint32_t)(rlo * 128 + kk2 * 2));
                    uint32_t o1 = SW128((uint32_t)((rlo + 8) * 128 + kk2 * 2));
                    *(__half*)(sm + o0) = __float2half_rn(v0);
                    *(__half*)(sm + o1) = __float2half_rn(v1);
                }
            __syncthreads();
            {   // stage (16KB, A0) -> g_h1img section ck=by
                const uint4* s4 = (const uint4*)sm;
                uint4* d4 = (uint4*)(g_h1img + (size_t)bx * 32768 + (size_t)by * 16384);
#pragma unroll
                for (int i = 0; i < 4; i++) d4[tid + i * 256] = s4[tid + i * 256];
            }
            // publish: all writes -> fence -> barrier -> single arrival
            __threadfence();
            __syncthreads();
            if (tid == 0) atomicAdd(&g_done[bx], 1);
        } else {
            // ================= layer2 + lin1 + lin2 tile =================
            const int bx = u - NL1;
            const int r0 = bx * 128;

            if (loadedB != 2) {   // once per CTA; overlaps the g_done spin below
                const char* gB = (const char*)g_W2sw;
#pragma unroll
                for (int i = 0; i < 8; i++) {
                    int idx = tid + i * 256;
                    cpa16(sb + 32768u + (uint32_t)idx * 16u, gB + (size_t)idx * 16);
                }
                CP_COMMIT();
                loadedB = 2;
            }

            if (tid == 0) {
                while (atomicAdd(&g_done[bx], 0) < 2) __nanosleep(64);
            }
            __syncthreads();   // acquire: flag seen -> h1img readable

            float acc[2][8][4];
#pragma unroll
            for (int mi = 0; mi < 2; mi++)
#pragma unroll
                for (int nj = 0; nj < 8; nj++)
#pragma unroll
                    for (int q = 0; q < 4; q++) acc[mi][nj][q] = 0.0f;

            {   // prologue: A0
                const char* gA = (const char*)g_h1img + (size_t)bx * 32768;
#pragma unroll
                for (int i = 0; i < 4; i++) {
                    int idx = tid + i * 256;
                    cpa16(sb + (uint32_t)idx * 16u, gA + (size_t)idx * 16);
                }
                CP_COMMIT();
            }

            for (int kt = 0; kt < 2; kt++) {
                const uint32_t aB = (uint32_t)kt * 16384u;
                const uint32_t bB = 32768u + (uint32_t)kt * 16384u;

                CP_WAIT0();
                __syncthreads();

                if (kt == 0) {   // prefetch A1 during chunk 0 compute
                    const char* gA = (const char*)g_h1img + (size_t)bx * 32768 + 16384;
#pragma unroll
                    for (int i = 0; i < 4; i++) {
                        int idx = tid + i * 256;
                        cpa16(sb + 16384u + (uint32_t)idx * 16u, gA + (size_t)idx * 16);
                    }
                    CP_COMMIT();
                }

#pragma unroll
                for (int kk = 0; kk < 4; kk++) {
                    uint32_t af[2][4], bfr[8][2];
#pragma unroll
                    for (int mi = 0; mi < 2; mi++) {
                        int row = arow0 + mi * 16;
                        uint32_t off = (uint32_t)(row * 128) + (((uint32_t)(kk * 32) + kba) ^ (uint32_t)((row & 7) << 4));
                        LDSM4(af[mi][0], af[mi][1], af[mi][2], af[mi][3], sb + aB + off);
                    }
#pragma unroll
                    for (int g = 0; g < 4; g++) {
                        int row = brow0 + g * 16;
                        uint32_t off = (uint32_t)(row * 128) + (((uint32_t)(kk * 32) + kbb) ^ (uint32_t)((row & 7) << 4));
                        LDSM4(bfr[2 * g][0], bfr[2 * g][1], bfr[2 * g + 1][0], bfr[2 * g + 1][1], sb + bB + off);
                    }
#pragma unroll
                    for (int mi = 0; mi < 2; mi++)
#pragma unroll
                        for (int nj = 0; nj < 8; nj++) mma_f16(acc[mi][nj], af[mi], bfr[nj]);
                }
            }

            // h2s (fp32, rotated cols) overlays [65536, 98304) — disjoint from A and W2,
            // so no barrier needed before writing.
            float* h2s = (float*)(sm + 65536);   // idx = row*64 + ((j + row) & 63)
#pragma unroll
            for (int mi = 0; mi < 2; mi++)
#pragma unroll
                for (int nj = 0; nj < 8; nj++) {
                    int rlo = wm * 32 + mi * 16 + (l >> 2);
                    int j = wn * 32 + nj * 4 + (l & 3);
                    float v0 = gate_act(acc[mi][nj][0] + bz2s[j], acc[mi][nj][1] + bh2s[j]);
                    float v1 = gate_act(acc[mi][nj][2] + bz2s[j], acc[mi][nj][3] + bh2s[j]);
                    h2s[rlo * 64 + ((j + rlo) & 63)] = v0;
                    h2s[(rlo + 8) * 64 + ((j + rlo + 8) & 63)] = v1;
                }
            __syncthreads();

            if (tid < 128) {
                float s[16];
#pragma unroll
                for (int uu = 0; uu < 16; uu++) s[uu] = b3s[uu];
#pragma unroll 4
                for (int j = 0; j < 64; j++) {
                    float v = h2s[tid * 64 + ((j + tid) & 63)];
#pragma unroll
                    for (int uu = 0; uu < 16; uu++) s[uu] = fmaf(v, w3s[j * 16 + uu], s[uu]);
                }
                float o2 = __ldg(b4);
#pragma unroll
                for (int uu = 0; uu < 16; uu++) o2 += fmaxf(s[uu], 0.0f) * w4s[uu];
                int gr = r0 + tid;
                if (gr < n) out[gr] = o2;
            }
            __syncthreads();   // h2s reads done before next unit reuses smem
        }
    }
}

extern "C" void kernel_launch(void* const* d_in, const int* in_sizes, int n_in,
                              void* d_out, int out_size) {
    const float* x   = (const float*)d_in[0];
    const float* wz1 = (const float*)d_in[3];
    const float* bz1 = (const float*)d_in[4];
    const float* wh1 = (const float*)d_in[7];
    const float* bh1 = (const float*)d_in[8];
    const float* wz2 = (const float*)d_in[9];
    const float* bz2 = (const float*)d_in[10];
    const float* wh2 = (const float*)d_in[13];
    const float* bh2 = (const float*)d_in[14];
    const float* w3  = (const float*)d_in[15];
    const float* b3  = (const float*)d_in[16];
    const float* w4  = (const float*)d_in[17];
    const float* b4  = (const float*)d_in[18];

    const int n  = in_sizes[0] / 256;          // 100000
    const int nb = (n + 127) / 128;            // 782

    int dev = 0, nsm = 148;
    cudaGetDevice(&dev);
    cudaDeviceGetAttribute(&nsm, cudaDevAttrMultiProcessorCount, dev);
    int grid = nsm * 2;                        // even => constant by-parity per CTA
    if (grid > nb * 2) grid = nb * 2;          // keep parity trick valid (stay even, <= NL1)

    cudaFuncSetAttribute(fused_persist, cudaFuncAttributeMaxDynamicSharedMemorySize, SM_BYTES);

    prep_kernel<<<256, 256>>>(wz1, wh1, wz2, wh2);
    fused_persist<<<grid, 256, SM_BYTES>>>(x, bz1, bh1, bz2, bh2, w3, b3, w4, b4,
                                           (float*)d_out, n, nb);
}